// round 14
// baseline (speedup 1.0000x reference)
#include <cuda_runtime.h>
#include <cuda_bf16.h>
#include <stdint.h>

#define NCORR    10000
#define MPAD     10048                 // 157*64
#define DEM_LEN  20480
#define NCHUNK_M 157
#define CHUNK_M  64
#define NPAD     10240
#define NTILES   (10 * 3 * NCHUNK_M)   // 4710
#define NPIX     16384
#define MTHETA   1184                  // θ-grid; ×4 n-chunks = 4736 tasks = #tail warps
#define NBLK     148
#define NBLK2    1184                  // corr blocks: 8 per SM exactly
#define NSLICE   79                    // 79*128 = 10112 >= NCORR
#define LOG2E    1.4426950408889634
#define RSQRT2   0.70710678118654752f
#define RSQRT6   0.40824829046386302f
#define SQRT2F   1.41421356237309505f
#define TWOPI    6.283185307179586476925286766559

typedef unsigned long long ull;

__device__ __forceinline__ ull pk(float lo, float hi) {
    ull r; asm("mov.b64 %0, {%1,%2};" : "=l"(r) : "f"(lo), "f"(hi)); return r;
}
__device__ __forceinline__ void upk(ull v, float& lo, float& hi) {
    asm("mov.b64 {%0,%1}, %2;" : "=f"(lo), "=f"(hi) : "l"(v));
}
__device__ __forceinline__ ull f2mul(ull a, ull b) {
    ull d; asm("mul.rn.f32x2 %0, %1, %2;" : "=l"(d) : "l"(a), "l"(b)); return d;
}
__device__ __forceinline__ ull f2add(ull a, ull b) {
    ull d; asm("add.rn.f32x2 %0, %1, %2;" : "=l"(d) : "l"(a), "l"(b)); return d;
}
__device__ __forceinline__ ull f2fma(ull a, ull b, ull c) {
    ull d; asm("fma.rn.f32x2 %0, %1, %2, %3;" : "=l"(d) : "l"(a), "l"(b), "l"(c)); return d;
}
__device__ __forceinline__ float ex2(float x) {
    float r; asm("ex2.approx.f32 %0, %1;" : "=f"(r) : "f"(x)); return r;
}

// ---------------- device scratch ----------------
__device__ float  g_modT[3][MPAD];
__device__ float  g_demT2[3][DEM_LEN];
__device__ float  g_part[3][NCHUNK_M][NPAD];
__device__ float  g_raw[3][NCORR];
__device__ double g_s6[6][5];                      // column-sum partials
__device__ double g_bs1[3][NSLICE], g_bs2[3][NSLICE]; // corr moment partials
__device__ __align__(16) float2 g_ps[MTHETA][4];   // per-(theta, n-chunk) partial (S, W)
__device__ int    g_tilectr;                       // corr tile counter
__device__ int    g_sync1;                         // corr barrier (1184), monotonic
__device__ int    g_sync2;                         // tail barrier (148), monotonic

// Monotonic-ticket grid barriers: replay-safe (never reset); all blocks resident.
__device__ __forceinline__ void grid_sync_n(int* ctr, int nblk) {
    __syncthreads();
    if (threadIdx.x == 0) {
        __threadfence();
        int t = atomicAdd(ctr, 1);
        int target = (t / nblk + 1) * nblk;
        while (*(volatile int*)ctr < target) {}
        __threadfence();
    }
    __syncthreads();
}

// ======== kernel 1: prep(phase0) + correlation(phase1) + partial-fold(phase2) ========
__global__ void __launch_bounds__(128, 8) corr_kernel(const float* __restrict__ Mod,
                                                      const float* __restrict__ Dem) {
    __shared__ __align__(16) float sdem[1120];
    __shared__ ull smod[64];
    __shared__ int s_tile;
    __shared__ double shd[128];
    const int tid = threadIdx.x, bid = blockIdx.x;

    // ---- phase 0: transpose+dup+pad (480 blocks) + fp64 col sums (30 blocks) ----
    {
        const int gidx = bid * 128 + tid;
        if (gidx == 0) g_tilectr = 0;
        if (gidx < 3 * DEM_LEN) {
            const int k = gidx / DEM_LEN, j = gidx % DEM_LEN;
            if (j < NCORR) {
                g_modT[k][j] = Mod[j * 3 + k];
                float d = Dem[j * 3 + k];
                g_demT2[k][j]         = d;
                g_demT2[k][j + NCORR] = d;
            } else {
                if (j < MPAD)       g_modT[k][j]  = 0.f;
                if (j >= 2 * NCORR) g_demT2[k][j] = 0.f;
            }
        }
        if (bid >= NBLK2 - 30) {                 // 30 blocks: 6 cols x 5 chunks
            const int b = bid - (NBLK2 - 30);
            const int col = b / 5, chunk = b % 5;
            const int k = col % 3;
            const float* src = (col < 3) ? Mod : Dem;
            const int base = chunk * 2000;
            double s = 0.0;
            for (int i = tid; i < 2000; i += 128) s += (double)src[(base + i) * 3 + k];
            shd[tid] = s; __syncthreads();
            for (int o = 64; o; o >>= 1) {
                if (tid < o) shd[tid] += shd[tid + o];
                __syncthreads();
            }
            if (tid == 0) g_s6[col][chunk] = shd[0];
        }
    }
    grid_sync_n(&g_sync1, NBLK2);

    // ---- phase 1: work-stealing correlation tiles ----
    while (true) {
        if (tid == 0) s_tile = atomicAdd(&g_tilectr, 1);
        __syncthreads();
        const int tile = s_tile;
        if (tile >= NTILES) break;
        const int nslice = tile % 10, rem = tile / 10;
        const int k = rem % 3, mc = rem / 3;
        const int n0 = nslice * 1024, m0 = mc * CHUNK_M;

        if (tid < CHUNK_M) { float v = g_modT[k][m0 + tid]; smod[tid] = pk(v, v); }
        for (int i = tid; i < 1104; i += 128) sdem[i] = g_demT2[k][m0 + n0 + i];
        __syncthreads();

        ull a0 = 0ull, a1 = 0ull, a2 = 0ull, a3 = 0ull;
        const ulonglong2* qp = reinterpret_cast<const ulonglong2*>(&sdem[8 * tid]);
        ulonglong2 qa = qp[0], qb = qp[1], qc = qp[2];
        ull P0 = qa.x, P1 = qa.y, P2 = qb.x, P3 = qb.y, P4 = qc.x, P5 = qc.y;
#pragma unroll 4
        for (int g = 0; g < 16; g++) {           // 16 groups x 4 m = 64 m
            ull mv0 = smod[4 * g], mv1 = smod[4 * g + 1],
                mv2 = smod[4 * g + 2], mv3 = smod[4 * g + 3];
            float w0, w1, w2, w3, w4, w5, w6, w7, w8, w9, w10, w11;
            upk(P0, w0, w1); upk(P1, w2, w3); upk(P2, w4, w5);
            upk(P3, w6, w7); upk(P4, w8, w9); upk(P5, w10, w11);
            ull B0 = pk(w1, w2), B1 = pk(w3, w4), B2 = pk(w5, w6),
                B3 = pk(w7, w8), B4 = pk(w9, w10);
            a0 = f2fma(mv0, P0, a0); a1 = f2fma(mv0, P1, a1);
            a2 = f2fma(mv0, P2, a2); a3 = f2fma(mv0, P3, a3);
            a0 = f2fma(mv1, B0, a0); a1 = f2fma(mv1, B1, a1);
            a2 = f2fma(mv1, B2, a2); a3 = f2fma(mv1, B3, a3);
            a0 = f2fma(mv2, P1, a0); a1 = f2fma(mv2, P2, a1);
            a2 = f2fma(mv2, P3, a2); a3 = f2fma(mv2, P4, a3);
            a0 = f2fma(mv3, B1, a0); a1 = f2fma(mv3, B2, a1);
            a2 = f2fma(mv3, B3, a2); a3 = f2fma(mv3, B4, a3);
            P0 = P2; P1 = P3; P2 = P4; P3 = P5;
            ulonglong2 qn = qp[g + 3];
            P4 = qn.x; P5 = qn.y;
        }
        {
            float o0, o1, o2, o3, o4, o5, o6, o7;
            upk(a0, o0, o1); upk(a1, o2, o3); upk(a2, o4, o5); upk(a3, o6, o7);
            float* dst = &g_part[k][mc][n0 + 8 * tid];
            *reinterpret_cast<float4*>(dst)     = make_float4(o0, o1, o2, o3);
            *reinterpret_cast<float4*>(dst + 4) = make_float4(o4, o5, o6, o7);
        }
        __syncthreads();
    }
    grid_sync_n(&g_sync1, NBLK2);

    // ---- phase 2: fold m-chunk partials + fp64 moments (237 blocks, 128 n each) ----
    if (bid < 3 * NSLICE) {
        const int k = bid / NSLICE, slice = bid % NSLICE;
        const int n = slice * 128 + tid;
        float acc = 0.f;
#pragma unroll 8
        for (int c = 0; c < NCHUNK_M; c++) acc += g_part[k][c][n];
        double x = 0.0;
        if (n < NCORR) { g_raw[k][n] = acc; x = (double)acc; }
        double s = x, sq = x * x;
#pragma unroll
        for (int o = 16; o; o >>= 1) {
            s  += __shfl_xor_sync(0xffffffffu, s,  o);
            sq += __shfl_xor_sync(0xffffffffu, sq, o);
        }
        __shared__ double sm1[4], sm2[4];
        if ((tid & 31) == 0) { sm1[tid >> 5] = s; sm2[tid >> 5] = sq; }
        __syncthreads();
        if (tid == 0) {
            g_bs1[k][slice] = sm1[0] + sm1[1] + sm1[2] + sm1[3];
            g_bs2[k][slice] = sm2[0] + sm2[1] + sm2[2] + sm2[3];
        }
    }
}

// ======== kernel 2: stats + build + theta decode + gather ========
__global__ void __launch_bounds__(1024, 1)
tail_kernel(const float* __restrict__ gt, float* __restrict__ out) {
    extern __shared__ __align__(16) char smem_raw[];
    const int tid = threadIdx.x, bid = blockIdx.x;

    // --- phase D: every block folds stats redundantly ---
    __shared__ float sh_scale[3], sh_mean[3], sh_amb[3];
    __shared__ double sh_sums6[6];
    {
        const int w = tid >> 5, lane = tid & 31;
        if (w < 6) {
            double s = (lane < 5) ? g_s6[w][lane] : 0.0;
#pragma unroll
            for (int o = 16; o; o >>= 1) s += __shfl_xor_sync(0xffffffffu, s, o);
            if (lane == 0) sh_sums6[w] = s;
        }
        __syncthreads();
        if (w < 3) {                               // fold 79 moment partials per k
            double s1 = g_bs1[w][lane] + g_bs1[w][lane + 32];
            double s2 = g_bs2[w][lane] + g_bs2[w][lane + 32];
            if (lane < 15) { s1 += g_bs1[w][lane + 64]; s2 += g_bs2[w][lane + 64]; }
#pragma unroll
            for (int o = 16; o; o >>= 1) {
                s1 += __shfl_xor_sync(0xffffffffu, s1, o);
                s2 += __shfl_xor_sync(0xffffffffu, s2, o);
            }
            if (lane == 0) {
                double mean = s1 / NCORR;
                double var  = (s2 - s1 * s1 / NCORR) / (NCORR - 1);
                double sgn  = (sh_sums6[w] < 0.0) ? -1.0 : 1.0;
                sh_scale[w] = (float)(sgn * LOG2E / sqrt(var));
                sh_mean[w]  = (float)mean;
            }
        }
        if (tid >= 96 && tid < 99) sh_amb[tid - 96] = (float)(1.0e6 * sh_sums6[3 + (tid - 96)]);
    }
    __syncthreads();

    // --- phase E: build SoA templates (u, v) into smem ---
    float* s_u = reinterpret_cast<float*>(smem_raw);
    float* s_v = s_u + 10048;
    {
        const float sc0 = sh_scale[0], sc1 = sh_scale[1], sc2 = sh_scale[2];
        const float mv0 = sh_mean[0],  mv1 = sh_mean[1],  mv2 = sh_mean[2];
        for (int n = tid; n < NCORR; n += 1024) {
            float c0 = sc0 * (g_raw[0][n] - mv0);
            float c1 = sc1 * (g_raw[1][n] - mv1);
            float c2 = sc2 * (g_raw[2][n] - mv2);
            s_u[n] = (c0 - c1) * RSQRT2;
            s_v[n] = (c0 + c1 - 2.f * c2) * RSQRT6;
        }
    }
    __syncthreads();

    // --- phase F: theta-grid decode — exactly 1 task per warp ---
    {
        const int lane = tid & 31;
        const int task = bid * 32 + (tid >> 5);
        const int j = task >> 2, chunk = task & 3;
        const int base = chunk * 2500;
        float sn_, cs_;
        sincosf((float)((double)j * (TWOPI / MTHETA)), &sn_, &cs_);
        const float p = SQRT2F * cs_, q = SQRT2F * sn_;
        const ull pp = pk(p, p), qq = pk(q, q);
        const ull c128 = pk(128.f, 128.f);

        ull sA = 0ull, sB = 0ull, wA = 0ull, wB = 0ull;
        const int nb = base + 4 * lane;
        ull nfA = pk((float)nb, (float)(nb + 1));
        ull nfB = pk((float)(nb + 2), (float)(nb + 3));
        const ulonglong2* pu = reinterpret_cast<const ulonglong2*>(&s_u[nb]);
        const ulonglong2* pv = reinterpret_cast<const ulonglong2*>(&s_v[nb]);

#pragma unroll 4
        for (int it = 0; it < 19; it++) {         // 19*128 = 2432 of 2500
            ulonglong2 U = pu[it * 32];
            ulonglong2 V = pv[it * 32];
            ull zA = f2fma(pp, U.x, f2mul(qq, V.x));
            ull zB = f2fma(pp, U.y, f2mul(qq, V.y));
            float a, b;
            upk(zA, a, b); ull eA = pk(ex2(a), ex2(b));
            upk(zB, a, b); ull eB = pk(ex2(a), ex2(b));
            sA = f2add(sA, eA);  sB = f2add(sB, eB);
            wA = f2fma(eA, nfA, wA); wB = f2fma(eB, nfB, wB);
            nfA = f2add(nfA, c128);  nfB = f2add(nfB, c128);
        }
        if (lane < 17) {                          // tail: 68 samples
            const int n = base + 2432 + 4 * lane;
            ulonglong2 U = *reinterpret_cast<const ulonglong2*>(&s_u[n]);
            ulonglong2 V = *reinterpret_cast<const ulonglong2*>(&s_v[n]);
            ull ntA = pk((float)n, (float)(n + 1));
            ull ntB = pk((float)(n + 2), (float)(n + 3));
            ull zA = f2fma(pp, U.x, f2mul(qq, V.x));
            ull zB = f2fma(pp, U.y, f2mul(qq, V.y));
            float a, b;
            upk(zA, a, b); ull eA = pk(ex2(a), ex2(b));
            upk(zB, a, b); ull eB = pk(ex2(a), ex2(b));
            sA = f2add(sA, eA);  sB = f2add(sB, eB);
            wA = f2fma(eA, ntA, wA); wB = f2fma(eB, ntB, wB);
        }
        float a, b, s, w;
        ull st = f2add(sA, sB), wt = f2add(wA, wB);
        upk(st, a, b); s = a + b;
        upk(wt, a, b); w = a + b;
#pragma unroll
        for (int o = 16; o; o >>= 1) {
            s += __shfl_xor_sync(0xffffffffu, s, o);
            w += __shfl_xor_sync(0xffffffffu, w, o);
        }
        if (lane == 0) g_ps[j][chunk] = make_float2(s, w);
    }
    grid_sync_n(&g_sync2, NBLK);

    // --- phase G: gather per pixel (atan2 + lerp) ---
    {
        const float amb0 = sh_amb[0], amb1 = sh_amb[1], amb2 = sh_amb[2];
        const float inv_dt = (float)(MTHETA / TWOPI);
        const int px = bid * 1024 + tid;
        if (px < NPIX) {
            int idx = (int)rintf(gt[px]);
            idx = min(max(idx, 0), NCORR - 1);
            float x = __ldcg(&g_raw[0][idx]) + amb0;
            float y = __ldcg(&g_raw[1][idx]) + amb1;
            float z = __ldcg(&g_raw[2][idx]) + amb2;
            float pv = (x - y);
            float qv = (x + y - 2.f * z) * (RSQRT6 / RSQRT2);
            float th = atan2f(qv, pv);
            if (th < 0.f) th += (float)TWOPI;
            float g = th * inv_dt;
            int j0 = (int)g;
            float f = g - (float)j0;
            if (j0 >= MTHETA) j0 -= MTHETA;
            int j1 = j0 + 1; if (j1 >= MTHETA) j1 -= MTHETA;
            const float4* q0 = reinterpret_cast<const float4*>(&g_ps[j0][0]);
            const float4* q1 = reinterpret_cast<const float4*>(&g_ps[j1][0]);
            float4 u0 = __ldcg(&q0[0]), u1 = __ldcg(&q0[1]);
            float4 v0 = __ldcg(&q1[0]), v1 = __ldcg(&q1[1]);
            float S0 = u0.x + u0.z + u1.x + u1.z;
            float W0 = u0.y + u0.w + u1.y + u1.w;
            float S1 = v0.x + v0.z + v1.x + v1.z;
            float W1 = v0.y + v0.w + v1.y + v1.w;
            float F0 = W0 / S0, F1 = W1 / S1;
            out[px] = fmaf(f, F1 - F0, F0);
        }
    }
}

extern "C" void kernel_launch(void* const* d_in, const int* in_sizes, int n_in,
                              void* d_out, int out_size) {
    const float* gt  = (const float*)d_in[0];
    const float* Mod = (const float*)d_in[1];
    const float* Dem = (const float*)d_in[2];
    float* out = (float*)d_out;

    corr_kernel<<<NBLK2, 128>>>(Mod, Dem);

    int smem = 98304;   // templates 80.4KB; 148 blocks -> 1/SM, spin-sync residency
    cudaFuncSetAttribute(tail_kernel, cudaFuncAttributeMaxDynamicSharedMemorySize, smem);
    tail_kernel<<<NBLK, 1024, smem>>>(gt, out);
}